// round 16
// baseline (speedup 1.0000x reference)
#include <cuda_runtime.h>
#include <cuda_fp16.h>
#include <cuda_bf16.h>
#include <cstdint>

#define NMAX 50048
#define EMAX 860032
#define SLOTS 96

typedef unsigned long long u64;
typedef unsigned int u32;
typedef unsigned short u16;

// ---------------- scratch ----------------------------------------------------
__device__ __half g_h1th[NMAX * 128];  // layer-1 out, fp16, [node][ch][head]
__device__ __half g_h2th[NMAX * 64];   // layer-2 out, fp16, [node][ch%32][ch/32]
__device__ u16    g_w1h[16384];        // W1^T bf16 hi, [n][k]
__device__ u16    g_w1l[16384];
__device__ u16    g_w2h[8192];         // W2^T bf16 hi, [n][k]
__device__ u16    g_w2l[8192];
__device__ float  g_as1[NMAX * 4];
__device__ float  g_ad1[NMAX * 4];
__device__ float  g_as2[NMAX];
__device__ float  g_ad2[NMAX];
__device__ int    g_cur[NMAX];
__device__ int    g_ell[NMAX * SLOTS];

// ---------------- helpers -----------------------------------------------------
__device__ __forceinline__ void cpasync16(void* dst, const void* src) {
    unsigned int d = (unsigned int)__cvta_generic_to_shared(dst);
    asm volatile("cp.async.cg.shared.global [%0], [%1], 16;" :: "r"(d), "l"(src));
}
#define CP_COMMIT() asm volatile("cp.async.commit_group;")
#define CP_WAIT0()  asm volatile("cp.async.wait_group 0;")
#define CP_WAIT1()  asm volatile("cp.async.wait_group 1;")

__device__ __forceinline__ u32 smem_u32(const void* p) {
    u32 a;
    asm("{ .reg .u64 t; cvta.to.shared.u64 t, %1; cvt.u32.u64 %0, t; }" : "=r"(a) : "l"(p));
    return a;
}
__device__ __forceinline__ void ldm4(u32 addr, u32& r0, u32& r1, u32& r2, u32& r3) {
    asm volatile("ldmatrix.sync.aligned.m8n8.x4.shared.b16 {%0,%1,%2,%3}, [%4];"
                 : "=r"(r0), "=r"(r1), "=r"(r2), "=r"(r3) : "r"(addr));
}
__device__ __forceinline__ void mma_bf16(float* d, const u32* a, u32 b0, u32 b1) {
    asm volatile("mma.sync.aligned.m16n8k16.row.col.f32.bf16.bf16.f32 "
                 "{%0,%1,%2,%3}, {%4,%5,%6,%7}, {%8,%9}, {%0,%1,%2,%3};"
                 : "+f"(d[0]), "+f"(d[1]), "+f"(d[2]), "+f"(d[3])
                 : "r"(a[0]), "r"(a[1]), "r"(a[2]), "r"(a[3]), "r"(b0), "r"(b1));
}
__device__ __forceinline__ void bfsplit(float v, u16& hi, u16& lo) {
    __nv_bfloat16 h = __float2bfloat16(v);
    float r = v - __bfloat162float(h);
    hi = __bfloat16_as_ushort(h);
    lo = __bfloat16_as_ushort(__float2bfloat16(r));
}

// smem layouts: gemm1 BM=64 -> A 32KB + B 64KB = 96KB (2 blocks/SM)
#define SM_AH 0
#define SM_AL 16384
#define SM_BH 32768
#define SM_BL 65536
#define SM_TOTAL 98304
// fused agg1+gemm2: BM=64, BN=64 -> 64KB
#define SM2_AH 0
#define SM2_AL 16384
#define SM2_BH 32768
#define SM2_BL 49152
#define SM2_TOTAL 65536

// ---------------- prep: zero g_cur + convert W1/W2 to bf16 hi/lo -------------
__global__ __launch_bounds__(256) void prep_kernel(
    const float* __restrict__ W1, const float* __restrict__ W2, int n, int zb)
{
    int b = blockIdx.x, tid = threadIdx.x;
    if (b < zb) {
        int i = b * 256 + tid;
        if (i < n) g_cur[i] = 0;
        return;
    }
    b -= zb;
    if (b < 8) {   // W1^T: [n][k], 16384 elems
        int base = b * 2048 + tid * 8;
        #pragma unroll
        for (int i = 0; i < 8; i++) {
            int e = base + i;
            int nr = e >> 7, k = e & 127;
            u16 h, l; bfsplit(W1[k * 128 + nr], h, l);
            g_w1h[e] = h; g_w1l[e] = l;
        }
        return;
    }
    b -= 8;
    if (b < 4) {   // W2^T: [n][k], 8192 elems
        int base = b * 2048 + tid * 8;
        #pragma unroll
        for (int i = 0; i < 8; i++) {
            int e = base + i;
            int nr = e >> 7, k = e & 127;
            u16 h, l; bfsplit(W2[k * 64 + nr], h, l);
            g_w2h[e] = h; g_w2l[e] = l;
        }
    }
}

// ---------------- GEMM1: BM=64, mma.sync 3-pass, K-pipelined + ELL fill ------
__global__ __launch_bounds__(256) void gemm1_fill_kernel(
    const float* __restrict__ x,
    const float* __restrict__ attS, const float* __restrict__ attD,
    const int* __restrict__ esrc, const int* __restrict__ edst,
    int M, int E, int gemmBlocks)
{
    extern __shared__ char smem[];
    int tid = threadIdx.x;

    if (blockIdx.x >= gemmBlocks) {
        int base = ((blockIdx.x - gemmBlocks) * 256 + tid) * 16;
        if (base + 15 < E) {
            #pragma unroll
            for (int h = 0; h < 4; h++) {
                int4 s = *(const int4*)(esrc + base + h * 4);
                int4 d = *(const int4*)(edst + base + h * 4);
                int p;
                p = atomicAdd(&g_cur[d.x], 1); if (p < SLOTS) g_ell[d.x * SLOTS + p] = s.x;
                p = atomicAdd(&g_cur[d.y], 1); if (p < SLOTS) g_ell[d.y * SLOTS + p] = s.y;
                p = atomicAdd(&g_cur[d.z], 1); if (p < SLOTS) g_ell[d.z * SLOTS + p] = s.z;
                p = atomicAdd(&g_cur[d.w], 1); if (p < SLOTS) g_ell[d.w * SLOTS + p] = s.w;
            }
        } else {
            int lim = base + 16; if (lim > E) lim = E;
            for (int e = base; e < lim; e++) {
                int dd = edst[e];
                int p = atomicAdd(&g_cur[dd], 1);
                if (p < SLOTS) g_ell[dd * SLOTS + p] = esrc[e];
            }
        }
        return;
    }

    u32 sb = smem_u32(smem);
    int lane = tid & 31, wid = tid >> 5;
    int wm = wid >> 2, wn = wid & 3;          // 2x4 warp grid, warp tile 32x32
    int rowBase = blockIdx.x * 64;

    // B (W1 hi/lo, 128x128) via cp.async, two K-half commit groups
    #pragma unroll
    for (int i = 0; i < 4; i++) {
        int idx = i * 256 + tid;              // 1024 = 128 rows x 8 c
        int row = idx >> 3, c = idx & 7;
        u32 dst = row * 256 + ((u32)(c ^ (row & 7)) << 4);
        cpasync16(smem + SM_BH + dst, g_w1h + row * 128 + c * 8);
        cpasync16(smem + SM_BL + dst, g_w1l + row * 128 + c * 8);
    }
    CP_COMMIT();
    #pragma unroll
    for (int i = 0; i < 4; i++) {
        int idx = i * 256 + tid;
        int row = idx >> 3, c = (idx & 7) | 8;
        u32 dst = row * 256 + ((u32)(c ^ (row & 7)) << 4);
        cpasync16(smem + SM_BH + dst, g_w1h + row * 128 + c * 8);
        cpasync16(smem + SM_BL + dst, g_w1l + row * 128 + c * 8);
    }
    CP_COMMIT();

    // A (64 rows): fp32 LDG -> bf16 hi/lo -> swizzled STS (overlaps B loads)
    #pragma unroll
    for (int i = 0; i < 8; i++) {
        int flat4 = i * 256 + tid;            // 2048 float4 groups
        int row = flat4 >> 5;
        int col4 = (flat4 & 31) * 4;
        float4 v = make_float4(0.f, 0.f, 0.f, 0.f);
        int gr = rowBase + row;
        if (gr < M) v = *(const float4*)(x + gr * 128 + col4);
        float fv[4] = {v.x, v.y, v.z, v.w};
        u64 hi = 0, lo = 0;
        #pragma unroll
        for (int q = 0; q < 4; q++) {
            u16 h, l; bfsplit(fv[q], h, l);
            hi |= (u64)h << (16 * q);
            lo |= (u64)l << (16 * q);
        }
        u32 off = row * 256 + ((u32)(((col4 >> 3) ^ (row & 7))) << 4) + (col4 & 4) * 2;
        *(u64*)(smem + SM_AH + off) = hi;
        *(u64*)(smem + SM_AL + off) = lo;
    }

    float acc[2][4][4];
    #pragma unroll
    for (int mt = 0; mt < 2; mt++)
        #pragma unroll
        for (int nt = 0; nt < 4; nt++)
            #pragma unroll
            for (int q = 0; q < 4; q++) acc[mt][nt][q] = 0.f;

    CP_WAIT1();
    __syncthreads();

    #pragma unroll
    for (int half = 0; half < 2; half++) {
        if (half == 1) { CP_WAIT0(); __syncthreads(); }
        #pragma unroll
        for (int kt2 = 0; kt2 < 4; kt2++) {
            int kt = half * 4 + kt2;
            u32 ahi[2][4], alo[2][4], bhi[2][4], blo[2][4];
            #pragma unroll
            for (int mt = 0; mt < 2; mt++) {
                int row = wm * 32 + mt * 16 + (lane & 15);
                int c = kt * 2 + (lane >> 4);
                u32 off = row * 256 + ((c ^ (row & 7)) << 4);
                ldm4(sb + SM_AH + off, ahi[mt][0], ahi[mt][1], ahi[mt][2], ahi[mt][3]);
                ldm4(sb + SM_AL + off, alo[mt][0], alo[mt][1], alo[mt][2], alo[mt][3]);
            }
            #pragma unroll
            for (int np = 0; np < 2; np++) {
                int nn = wn * 32 + np * 16 + ((lane >> 4) << 3) + (lane & 7);
                int c = kt * 2 + ((lane >> 3) & 1);
                u32 off = nn * 256 + ((c ^ (nn & 7)) << 4);
                ldm4(sb + SM_BH + off, bhi[np][0], bhi[np][1], bhi[np][2], bhi[np][3]);
                ldm4(sb + SM_BL + off, blo[np][0], blo[np][1], blo[np][2], blo[np][3]);
            }
            #pragma unroll
            for (int mt = 0; mt < 2; mt++)
                #pragma unroll
                for (int nt = 0; nt < 4; nt++) {
                    int np = nt >> 1, sel = (nt & 1) * 2;
                    mma_bf16(acc[mt][nt], ahi[mt], bhi[np][sel], bhi[np][sel + 1]);
                    mma_bf16(acc[mt][nt], ahi[mt], blo[np][sel], blo[np][sel + 1]);
                    mma_bf16(acc[mt][nt], alo[mt], bhi[np][sel], bhi[np][sel + 1]);
                }
        }
    }
    __syncthreads();

    // stage H fp32 [64][128] stride 512B (reuses A region, 32KB)
    #pragma unroll
    for (int mt = 0; mt < 2; mt++)
        #pragma unroll
        for (int nt = 0; nt < 4; nt++) {
            int r0 = wm * 32 + mt * 16 + (lane >> 2);
            int c0 = wn * 32 + nt * 8 + (lane & 3) * 2;
            *(float2*)(smem + r0 * 512 + c0 * 4) = make_float2(acc[mt][nt][0], acc[mt][nt][1]);
            *(float2*)(smem + (r0 + 8) * 512 + c0 * 4) = make_float2(acc[mt][nt][2], acc[mt][nt][3]);
        }
    __syncthreads();

    // att1 sums: warp w handles rows w*8..w*8+7
    float aS0 = attS[lane], aS1 = attS[32 + lane], aS2 = attS[64 + lane], aS3 = attS[96 + lane];
    float aD0 = attD[lane], aD1 = attD[32 + lane], aD2 = attD[64 + lane], aD3 = attD[96 + lane];
    for (int rr = 0; rr < 8; rr++) {
        int r = wid * 8 + rr;
        int gr = rowBase + r;
        const float* hp = (const float*)(smem + r * 512);
        float h0 = hp[lane], h1 = hp[32 + lane], h2 = hp[64 + lane], h3 = hp[96 + lane];
        float s0 = h0 * aS0, s1 = h1 * aS1, s2 = h2 * aS2, s3 = h3 * aS3;
        float d0 = h0 * aD0, d1 = h1 * aD1, d2 = h2 * aD2, d3 = h3 * aD3;
        #pragma unroll
        for (int o = 16; o; o >>= 1) {
            s0 += __shfl_xor_sync(0xffffffffu, s0, o);
            s1 += __shfl_xor_sync(0xffffffffu, s1, o);
            s2 += __shfl_xor_sync(0xffffffffu, s2, o);
            s3 += __shfl_xor_sync(0xffffffffu, s3, o);
            d0 += __shfl_xor_sync(0xffffffffu, d0, o);
            d1 += __shfl_xor_sync(0xffffffffu, d1, o);
            d2 += __shfl_xor_sync(0xffffffffu, d2, o);
            d3 += __shfl_xor_sync(0xffffffffu, d3, o);
        }
        if (lane == 0 && gr < M) {
            *(float4*)(g_as1 + gr * 4) = make_float4(s0, s1, s2, s3);
            *(float4*)(g_ad1 + gr * 4) = make_float4(d0, d1, d2, d3);
        }
    }

    // h1th store: 2048 = 64 rows x 32 ch
    #pragma unroll
    for (int i = 0; i < 8; i++) {
        int idx = i * 256 + tid;
        int r = idx >> 5, ch = idx & 31;
        int gr = rowBase + r;
        if (gr < M) {
            const float* hp = (const float*)(smem + r * 512);
            u64 pk = (u64)__half_as_ushort(__float2half_rn(hp[ch]))
                   | ((u64)__half_as_ushort(__float2half_rn(hp[32 + ch])) << 16)
                   | ((u64)__half_as_ushort(__float2half_rn(hp[64 + ch])) << 32)
                   | ((u64)__half_as_ushort(__float2half_rn(hp[96 + ch])) << 48);
            *(u64*)(g_h1th + gr * 128 + ch * 4) = pk;
        }
    }
}

// ---------------- fused agg1 + GEMM2 (+att2 epi) -----------------------------
// aggregation: 2 edges per warp-iteration (16-lane edge groups, 2ch x 4 heads/lane)
__global__ __launch_bounds__(256) void agg1_gemm2_kernel(
    const float* __restrict__ b1,
    const float* __restrict__ attS, const float* __restrict__ attD, int M)
{
    extern __shared__ char smem[];
    __shared__ float4 wbuf[8][32];
    __shared__ int    sbuf[8][32];
    u32 sb = smem_u32(smem);
    int tid = threadIdx.x, lane = tid & 31, wid = tid >> 5;
    int wm = wid >> 2, wn = wid & 3;          // 2x4 warp grid, warp tile 32x16
    int rowBase = blockIdx.x * 64;
    int eh = lane >> 4, lc = lane & 15;       // edge-of-pair, channel chunk

    // B (W2 hi/lo, 64x128) via cp.async — overlaps the whole aggregation phase
    #pragma unroll
    for (int i = 0; i < 4; i++) {
        int idx = i * 256 + tid;              // 1024 = 64 rows x 16 c
        int row = idx >> 4, c = idx & 15;
        u32 dst = row * 256 + ((u32)(c ^ (row & 7)) << 4);
        cpasync16(smem + SM2_BH + dst, g_w2h + row * 128 + c * 8);
        cpasync16(smem + SM2_BL + dst, g_w2l + row * 128 + c * 8);
    }
    CP_COMMIT();

    // hoisted b1 values: lane lc owns ch lc*2, lc*2+1, heads 0..3
    float b1v[2][4];
    #pragma unroll
    for (int c = 0; c < 2; c++)
        #pragma unroll
        for (int h = 0; h < 4; h++) b1v[c][h] = b1[h * 32 + lc * 2 + c];

    const char* h1b = (const char*)g_h1th;
    for (int t = 0; t < 8; t++) {
        int r = wid * 8 + t;
        int node = rowBase + r;
        if (node >= M) break;
        float4 ad = *(const float4*)(g_ad1 + node * 4);
        int deg = g_cur[node]; if (deg > SLOTS) deg = SLOTS;
        const int* ep = g_ell + node * SLOTS;
        float s0 = 0.f, s1 = 0.f, s2 = 0.f, s3 = 0.f;
        float ca[2][4];
        #pragma unroll
        for (int c = 0; c < 2; c++)
            #pragma unroll
            for (int h = 0; h < 4; h++) ca[c][h] = 0.f;

        for (int base = 0; base < deg; base += 32) {
            int i = base + lane;
            float4 wv = make_float4(0.f, 0.f, 0.f, 0.f);
            int off = 0;
            if (i < deg) {
                int src = ep[i];
                float4 asv = *(const float4*)(g_as1 + src * 4);
                float e;
                e = asv.x + ad.x; e = e > 0.f ? e : 0.2f * e; wv.x = __expf(fminf(e, 80.f));
                e = asv.y + ad.y; e = e > 0.f ? e : 0.2f * e; wv.y = __expf(fminf(e, 80.f));
                e = asv.z + ad.z; e = e > 0.f ? e : 0.2f * e; wv.z = __expf(fminf(e, 80.f));
                e = asv.w + ad.w; e = e > 0.f ? e : 0.2f * e; wv.w = __expf(fminf(e, 80.f));
                off = src * 256;              // byte offset of h1th row
            }
            wbuf[wid][lane] = wv;
            sbuf[wid][lane] = off;
            __syncwarp();
            int cnt = deg - base; if (cnt > 32) cnt = 32;
            int cnt2 = (cnt + 1) & ~1;        // pad: staged w=0,off=0
            for (int j = 0; j < cnt2; j += 2) {
                float4 q = wbuf[wid][j + eh];
                uint4 pk = *(const uint4*)(h1b + sbuf[wid][j + eh] + lc * 16);
                float2 f0 = __half22float2(*(__half2*)&pk.x);  // ch lc*2, heads 0,1
                float2 f1 = __half22float2(*(__half2*)&pk.y);  // ch lc*2, heads 2,3
                float2 f2 = __half22float2(*(__half2*)&pk.z);  // ch lc*2+1, heads 0,1
                float2 f3 = __half22float2(*(__half2*)&pk.w);  // ch lc*2+1, heads 2,3
                s0 += q.x; s1 += q.y; s2 += q.z; s3 += q.w;
                ca[0][0] = fmaf(q.x, f0.x, ca[0][0]); ca[0][1] = fmaf(q.y, f0.y, ca[0][1]);
                ca[0][2] = fmaf(q.z, f1.x, ca[0][2]); ca[0][3] = fmaf(q.w, f1.y, ca[0][3]);
                ca[1][0] = fmaf(q.x, f2.x, ca[1][0]); ca[1][1] = fmaf(q.y, f2.y, ca[1][1]);
                ca[1][2] = fmaf(q.z, f3.x, ca[1][2]); ca[1][3] = fmaf(q.w, f3.y, ca[1][3]);
            }
            __syncwarp();
        }
        // combine the two edge groups
        s0 += __shfl_xor_sync(0xffffffffu, s0, 16);
        s1 += __shfl_xor_sync(0xffffffffu, s1, 16);
        s2 += __shfl_xor_sync(0xffffffffu, s2, 16);
        s3 += __shfl_xor_sync(0xffffffffu, s3, 16);
        #pragma unroll
        for (int c = 0; c < 2; c++)
            #pragma unroll
            for (int h = 0; h < 4; h++)
                ca[c][h] += __shfl_xor_sync(0xffffffffu, ca[c][h], 16);

        if (eh == 0) {
            float sv[4] = {s0, s1, s2, s3};
            #pragma unroll
            for (int c = 0; c < 2; c++)
                #pragma unroll
                for (int h = 0; h < 4; h++) {
                    float o = fmaxf(ca[c][h] / sv[h] + b1v[c][h], 0.f);
                    u16 hh, ll; bfsplit(o, hh, ll);
                    int cc = h * 32 + lc * 2 + c;
                    u32 off = r * 256 + ((u32)(((cc >> 3) ^ (r & 7))) << 4) + (cc & 7) * 2;
                    *(u16*)(smem + SM2_AH + off) = hh;
                    *(u16*)(smem + SM2_AL + off) = ll;
                }
        }
    }
    CP_WAIT0();
    __syncthreads();

    // ---- GEMM: hmid(smem) @ W2 ----
    float acc[2][2][4];
    #pragma unroll
    for (int mt = 0; mt < 2; mt++)
        #pragma unroll
        for (int nt = 0; nt < 2; nt++)
            #pragma unroll
            for (int q = 0; q < 4; q++) acc[mt][nt][q] = 0.f;

    #pragma unroll
    for (int kt = 0; kt < 8; kt++) {
        u32 ahi[2][4], alo[2][4], bhi[4], blo[4];
        #pragma unroll
        for (int mt = 0; mt < 2; mt++) {
            int row = wm * 32 + mt * 16 + (lane & 15);
            int c = kt * 2 + (lane >> 4);
            u32 off = row * 256 + ((c ^ (row & 7)) << 4);
            ldm4(sb + SM2_AH + off, ahi[mt][0], ahi[mt][1], ahi[mt][2], ahi[mt][3]);
            ldm4(sb + SM2_AL + off, alo[mt][0], alo[mt][1], alo[mt][2], alo[mt][3]);
        }
        {
            int nn = wn * 16 + ((lane >> 4) << 3) + (lane & 7);
            int c = kt * 2 + ((lane >> 3) & 1);
            u32 off = nn * 256 + ((c ^ (nn & 7)) << 4);
            ldm4(sb + SM2_BH + off, bhi[0], bhi[1], bhi[2], bhi[3]);
            ldm4(sb + SM2_BL + off, blo[0], blo[1], blo[2], blo[3]);
        }
        #pragma unroll
        for (int mt = 0; mt < 2; mt++)
            #pragma unroll
            for (int nt = 0; nt < 2; nt++) {
                int sel = nt * 2;
                mma_bf16(acc[mt][nt], ahi[mt], bhi[sel], bhi[sel + 1]);
                mma_bf16(acc[mt][nt], ahi[mt], blo[sel], blo[sel + 1]);
                mma_bf16(acc[mt][nt], alo[mt], bhi[sel], bhi[sel + 1]);
            }
    }
    __syncthreads();

    // stage H fp32 [64][64] stride 256B (reuses A region)
    #pragma unroll
    for (int mt = 0; mt < 2; mt++)
        #pragma unroll
        for (int nt = 0; nt < 2; nt++) {
            int r0 = wm * 32 + mt * 16 + (lane >> 2);
            int c0 = wn * 16 + nt * 8 + (lane & 3) * 2;
            *(float2*)(smem + r0 * 256 + c0 * 4) = make_float2(acc[mt][nt][0], acc[mt][nt][1]);
            *(float2*)(smem + (r0 + 8) * 256 + c0 * 4) = make_float2(acc[mt][nt][2], acc[mt][nt][3]);
        }
    __syncthreads();

    float aS0 = attS[lane], aS1 = attS[32 + lane];
    float aD0 = attD[lane], aD1 = attD[32 + lane];
    for (int rr = 0; rr < 8; rr++) {
        int r = wid * 8 + rr;
        int gr = rowBase + r;
        const float* hp = (const float*)(smem + r * 256);
        float h0 = hp[lane], h1 = hp[32 + lane];
        float sp = h0 * aS0 + h1 * aS1;
        float dp = h0 * aD0 + h1 * aD1;
        #pragma unroll
        for (int o = 16; o; o >>= 1) {
            sp += __shfl_xor_sync(0xffffffffu, sp, o);
            dp += __shfl_xor_sync(0xffffffffu, dp, o);
        }
        if (gr < M) {
            *(__half2*)(g_h2th + gr * 64 + lane * 2) = __floats2half2_rn(h0, h1);
            if (lane == 0) { g_as2[gr] = sp; g_ad2[gr] = dp; }
        }
    }
}

// ---------------- agg2: 2 edges per warp-iteration ---------------------------
__global__ __launch_bounds__(256) void agg2_kernel(const float* __restrict__ b2,
                                                   float* __restrict__ out, int n) {
    __shared__ float2 wbuf[8][32];
    int w = threadIdx.x >> 5, lane = threadIdx.x & 31;
    int node = blockIdx.x * 8 + w;
    if (node >= n) return;
    float ad = g_ad2[node];
    int deg = g_cur[node]; if (deg > SLOTS) deg = SLOTS;
    const int* ep = g_ell + node * SLOTS;
    const char* h2b = (const char*)g_h2th;
    int eh = lane >> 4, lc = lane & 15;
    float s = 0.f, a0 = 0.f, a1 = 0.f, a2 = 0.f, a3 = 0.f;

    for (int base = 0; base < deg; base += 32) {
        int i = base + lane;
        float wv = 0.f; int off = 0;
        if (i < deg) {
            int src = ep[i];
            float e = g_as2[src] + ad;
            e = e > 0.f ? e : 0.2f * e;
            wv = __expf(fminf(e, 80.f));
            off = src * 128;                  // byte offset of h2th row
        }
        wbuf[w][lane] = make_float2(wv, __int_as_float(off));
        __syncwarp();
        int cnt = deg - base; if (cnt > 32) cnt = 32;
        int cnt4 = (cnt + 3) & ~3;
        for (int j = 0; j < cnt4; j += 4) {
            #pragma unroll
            for (int u = 0; u < 4; u += 2) {
                float2 qo = wbuf[w][j + u + eh];
                float q = qo.x;
                const __half2* hp = (const __half2*)(h2b + __float_as_int(qo.y) + lc * 8);
                float2 v01 = __half22float2(hp[0]);  // ch lc*2, lc*2+32
                float2 v23 = __half22float2(hp[1]);  // ch lc*2+1, lc*2+33
                s += q;
                a0 = fmaf(q, v01.x, a0); a1 = fmaf(q, v01.y, a1);
                a2 = fmaf(q, v23.x, a2); a3 = fmaf(q, v23.y, a3);
            }
        }
        __syncwarp();
    }
    // combine edge groups
    s  += __shfl_xor_sync(0xffffffffu, s, 16);
    a0 += __shfl_xor_sync(0xffffffffu, a0, 16);
    a1 += __shfl_xor_sync(0xffffffffu, a1, 16);
    a2 += __shfl_xor_sync(0xffffffffu, a2, 16);
    a3 += __shfl_xor_sync(0xffffffffu, a3, 16);
    if (eh == 0) {
        float r = 1.f / s;
        *(float2*)(out + node * 64 + lc * 2) =
            make_float2(a0 * r + b2[lc * 2], a2 * r + b2[lc * 2 + 1]);
        *(float2*)(out + node * 64 + 32 + lc * 2) =
            make_float2(a1 * r + b2[32 + lc * 2], a3 * r + b2[32 + lc * 2 + 1]);
    }
}

// ---------------- launch -----------------------------------------------------
extern "C" void kernel_launch(void* const* d_in, const int* in_sizes, int n_in,
                              void* d_out, int out_size) {
    const float* x    = (const float*)d_in[0];
    const int*   esrc = (const int*)d_in[1];
    const int*   edst = (const int*)d_in[2];
    const float* W1   = (const float*)d_in[3];
    const float* as1w = (const float*)d_in[4];
    const float* ad1w = (const float*)d_in[5];
    const float* b1   = (const float*)d_in[6];
    const float* W2   = (const float*)d_in[7];
    const float* as2w = (const float*)d_in[8];
    const float* ad2w = (const float*)d_in[9];
    const float* b2   = (const float*)d_in[10];
    float* out = (float*)d_out;

    int n = in_sizes[0] / 128;
    int E = in_sizes[1];

    cudaFuncSetAttribute(gemm1_fill_kernel,
                         cudaFuncAttributeMaxDynamicSharedMemorySize, SM_TOTAL);
    cudaFuncSetAttribute(agg1_gemm2_kernel,
                         cudaFuncAttributeMaxDynamicSharedMemorySize, SM2_TOTAL);

    int zb = (n + 255) / 256;
    prep_kernel<<<zb + 12, 256>>>(W1, W2, n, zb);

    int gemmBlocks = (n + 63) / 64;
    int fillBlocks = (E + 4095) / 4096;
    gemm1_fill_kernel<<<gemmBlocks + fillBlocks, 256, SM_TOTAL>>>(
        x, as1w, ad1w, esrc, edst, n, E, gemmBlocks);
    agg1_gemm2_kernel<<<gemmBlocks, 256, SM2_TOTAL>>>(b1, as2w, ad2w, n);
    int aggBlocks = (n + 7) / 8;
    agg2_kernel<<<aggBlocks, 256>>>(b2, out, n);
}

// round 17
// speedup vs baseline: 1.0822x; 1.0822x over previous
#include <cuda_runtime.h>
#include <cuda_fp16.h>
#include <cuda_bf16.h>
#include <cstdint>

#define NMAX 50048
#define EMAX 860032
#define SLOTS 96

typedef unsigned long long u64;
typedef unsigned int u32;
typedef unsigned short u16;

// ---------------- scratch ----------------------------------------------------
__device__ __half g_h1th[NMAX * 128];  // layer-1 out, fp16, [node][ch][head]
__device__ __half g_h2th[NMAX * 64];   // layer-2 out, fp16, [node][ch%32][ch/32]
__device__ u16    g_w1h[16384];        // W1^T bf16 hi, [n][k]
__device__ u16    g_w1l[16384];
__device__ u16    g_w2h[8192];         // W2^T bf16 hi, [n][k]
__device__ u16    g_w2l[8192];
__device__ float  g_as1[NMAX * 4];
__device__ float  g_ad1[NMAX * 4];
__device__ float  g_as2[NMAX];
__device__ float  g_ad2[NMAX];
__device__ int    g_cur[NMAX];
__device__ int    g_ell[NMAX * SLOTS];

// ---------------- helpers -----------------------------------------------------
__device__ __forceinline__ void cpasync16(void* dst, const void* src) {
    unsigned int d = (unsigned int)__cvta_generic_to_shared(dst);
    asm volatile("cp.async.cg.shared.global [%0], [%1], 16;" :: "r"(d), "l"(src));
}
#define CP_COMMIT() asm volatile("cp.async.commit_group;")
#define CP_WAIT0()  asm volatile("cp.async.wait_group 0;")
#define CP_WAIT1()  asm volatile("cp.async.wait_group 1;")

__device__ __forceinline__ u32 smem_u32(const void* p) {
    u32 a;
    asm("{ .reg .u64 t; cvta.to.shared.u64 t, %1; cvt.u32.u64 %0, t; }" : "=r"(a) : "l"(p));
    return a;
}
__device__ __forceinline__ void ldm4(u32 addr, u32& r0, u32& r1, u32& r2, u32& r3) {
    asm volatile("ldmatrix.sync.aligned.m8n8.x4.shared.b16 {%0,%1,%2,%3}, [%4];"
                 : "=r"(r0), "=r"(r1), "=r"(r2), "=r"(r3) : "r"(addr));
}
__device__ __forceinline__ void mma_bf16(float* d, const u32* a, u32 b0, u32 b1) {
    asm volatile("mma.sync.aligned.m16n8k16.row.col.f32.bf16.bf16.f32 "
                 "{%0,%1,%2,%3}, {%4,%5,%6,%7}, {%8,%9}, {%0,%1,%2,%3};"
                 : "+f"(d[0]), "+f"(d[1]), "+f"(d[2]), "+f"(d[3])
                 : "r"(a[0]), "r"(a[1]), "r"(a[2]), "r"(a[3]), "r"(b0), "r"(b1));
}
__device__ __forceinline__ void bfsplit(float v, u16& hi, u16& lo) {
    __nv_bfloat16 h = __float2bfloat16(v);
    float r = v - __bfloat162float(h);
    hi = __bfloat16_as_ushort(h);
    lo = __bfloat16_as_ushort(__float2bfloat16(r));
}

// smem layouts: gemm1 BM=64 -> A 32KB + B 64KB = 96KB (2 blocks/SM)
#define SM_AH 0
#define SM_AL 16384
#define SM_BH 32768
#define SM_BL 65536
#define SM_TOTAL 98304
// fused agg1+gemm2: BM=64, BN=64 -> 64KB
#define SM2_AH 0
#define SM2_AL 16384
#define SM2_BH 32768
#define SM2_BL 49152
#define SM2_TOTAL 65536

// ---------------- prep: zero g_cur + convert W1/W2 to bf16 hi/lo -------------
__global__ __launch_bounds__(256) void prep_kernel(
    const float* __restrict__ W1, const float* __restrict__ W2, int n, int zb)
{
    int b = blockIdx.x, tid = threadIdx.x;
    if (b < zb) {
        int i = b * 256 + tid;
        if (i < n) g_cur[i] = 0;
        return;
    }
    b -= zb;
    if (b < 8) {   // W1^T: [n][k], 16384 elems
        int base = b * 2048 + tid * 8;
        #pragma unroll
        for (int i = 0; i < 8; i++) {
            int e = base + i;
            int nr = e >> 7, k = e & 127;
            u16 h, l; bfsplit(W1[k * 128 + nr], h, l);
            g_w1h[e] = h; g_w1l[e] = l;
        }
        return;
    }
    b -= 8;
    if (b < 4) {   // W2^T: [n][k], 8192 elems
        int base = b * 2048 + tid * 8;
        #pragma unroll
        for (int i = 0; i < 8; i++) {
            int e = base + i;
            int nr = e >> 7, k = e & 127;
            u16 h, l; bfsplit(W2[k * 64 + nr], h, l);
            g_w2h[e] = h; g_w2l[e] = l;
        }
    }
}

// ---------------- GEMM1: BM=64, mma.sync 3-pass, K-pipelined + ELL fill ------
__global__ __launch_bounds__(256) void gemm1_fill_kernel(
    const float* __restrict__ x,
    const float* __restrict__ attS, const float* __restrict__ attD,
    const int* __restrict__ esrc, const int* __restrict__ edst,
    int M, int E, int gemmBlocks)
{
    extern __shared__ char smem[];
    int tid = threadIdx.x;

    if (blockIdx.x >= gemmBlocks) {
        int base = ((blockIdx.x - gemmBlocks) * 256 + tid) * 16;
        if (base + 15 < E) {
            #pragma unroll
            for (int h = 0; h < 4; h++) {
                int4 s = *(const int4*)(esrc + base + h * 4);
                int4 d = *(const int4*)(edst + base + h * 4);
                int p;
                p = atomicAdd(&g_cur[d.x], 1); if (p < SLOTS) g_ell[d.x * SLOTS + p] = s.x;
                p = atomicAdd(&g_cur[d.y], 1); if (p < SLOTS) g_ell[d.y * SLOTS + p] = s.y;
                p = atomicAdd(&g_cur[d.z], 1); if (p < SLOTS) g_ell[d.z * SLOTS + p] = s.z;
                p = atomicAdd(&g_cur[d.w], 1); if (p < SLOTS) g_ell[d.w * SLOTS + p] = s.w;
            }
        } else {
            int lim = base + 16; if (lim > E) lim = E;
            for (int e = base; e < lim; e++) {
                int dd = edst[e];
                int p = atomicAdd(&g_cur[dd], 1);
                if (p < SLOTS) g_ell[dd * SLOTS + p] = esrc[e];
            }
        }
        return;
    }

    u32 sb = smem_u32(smem);
    int lane = tid & 31, wid = tid >> 5;
    int wm = wid >> 2, wn = wid & 3;          // 2x4 warp grid, warp tile 32x32
    int rowBase = blockIdx.x * 64;

    // B (W1 hi/lo, 128x128) via cp.async, two K-half commit groups
    #pragma unroll
    for (int i = 0; i < 4; i++) {
        int idx = i * 256 + tid;              // 1024 = 128 rows x 8 c
        int row = idx >> 3, c = idx & 7;
        u32 dst = row * 256 + ((u32)(c ^ (row & 7)) << 4);
        cpasync16(smem + SM_BH + dst, g_w1h + row * 128 + c * 8);
        cpasync16(smem + SM_BL + dst, g_w1l + row * 128 + c * 8);
    }
    CP_COMMIT();
    #pragma unroll
    for (int i = 0; i < 4; i++) {
        int idx = i * 256 + tid;
        int row = idx >> 3, c = (idx & 7) | 8;
        u32 dst = row * 256 + ((u32)(c ^ (row & 7)) << 4);
        cpasync16(smem + SM_BH + dst, g_w1h + row * 128 + c * 8);
        cpasync16(smem + SM_BL + dst, g_w1l + row * 128 + c * 8);
    }
    CP_COMMIT();

    // A (64 rows): fp32 LDG -> bf16 hi/lo -> swizzled STS (overlaps B loads)
    #pragma unroll
    for (int i = 0; i < 8; i++) {
        int flat4 = i * 256 + tid;            // 2048 float4 groups
        int row = flat4 >> 5;
        int col4 = (flat4 & 31) * 4;
        float4 v = make_float4(0.f, 0.f, 0.f, 0.f);
        int gr = rowBase + row;
        if (gr < M) v = *(const float4*)(x + gr * 128 + col4);
        float fv[4] = {v.x, v.y, v.z, v.w};
        u64 hi = 0, lo = 0;
        #pragma unroll
        for (int q = 0; q < 4; q++) {
            u16 h, l; bfsplit(fv[q], h, l);
            hi |= (u64)h << (16 * q);
            lo |= (u64)l << (16 * q);
        }
        u32 off = row * 256 + ((u32)(((col4 >> 3) ^ (row & 7))) << 4) + (col4 & 4) * 2;
        *(u64*)(smem + SM_AH + off) = hi;
        *(u64*)(smem + SM_AL + off) = lo;
    }

    float acc[2][4][4];
    #pragma unroll
    for (int mt = 0; mt < 2; mt++)
        #pragma unroll
        for (int nt = 0; nt < 4; nt++)
            #pragma unroll
            for (int q = 0; q < 4; q++) acc[mt][nt][q] = 0.f;

    CP_WAIT1();
    __syncthreads();

    #pragma unroll
    for (int half = 0; half < 2; half++) {
        if (half == 1) { CP_WAIT0(); __syncthreads(); }
        #pragma unroll
        for (int kt2 = 0; kt2 < 4; kt2++) {
            int kt = half * 4 + kt2;
            u32 ahi[2][4], alo[2][4], bhi[2][4], blo[2][4];
            #pragma unroll
            for (int mt = 0; mt < 2; mt++) {
                int row = wm * 32 + mt * 16 + (lane & 15);
                int c = kt * 2 + (lane >> 4);
                u32 off = row * 256 + ((c ^ (row & 7)) << 4);
                ldm4(sb + SM_AH + off, ahi[mt][0], ahi[mt][1], ahi[mt][2], ahi[mt][3]);
                ldm4(sb + SM_AL + off, alo[mt][0], alo[mt][1], alo[mt][2], alo[mt][3]);
            }
            #pragma unroll
            for (int np = 0; np < 2; np++) {
                int nn = wn * 32 + np * 16 + ((lane >> 4) << 3) + (lane & 7);
                int c = kt * 2 + ((lane >> 3) & 1);
                u32 off = nn * 256 + ((c ^ (nn & 7)) << 4);
                ldm4(sb + SM_BH + off, bhi[np][0], bhi[np][1], bhi[np][2], bhi[np][3]);
                ldm4(sb + SM_BL + off, blo[np][0], blo[np][1], blo[np][2], blo[np][3]);
            }
            #pragma unroll
            for (int mt = 0; mt < 2; mt++)
                #pragma unroll
                for (int nt = 0; nt < 4; nt++) {
                    int np = nt >> 1, sel = (nt & 1) * 2;
                    mma_bf16(acc[mt][nt], ahi[mt], bhi[np][sel], bhi[np][sel + 1]);
                    mma_bf16(acc[mt][nt], ahi[mt], blo[np][sel], blo[np][sel + 1]);
                    mma_bf16(acc[mt][nt], alo[mt], bhi[np][sel], bhi[np][sel + 1]);
                }
        }
    }
    __syncthreads();

    // stage H fp32 [64][128] stride 512B (reuses A region, 32KB)
    #pragma unroll
    for (int mt = 0; mt < 2; mt++)
        #pragma unroll
        for (int nt = 0; nt < 4; nt++) {
            int r0 = wm * 32 + mt * 16 + (lane >> 2);
            int c0 = wn * 32 + nt * 8 + (lane & 3) * 2;
            *(float2*)(smem + r0 * 512 + c0 * 4) = make_float2(acc[mt][nt][0], acc[mt][nt][1]);
            *(float2*)(smem + (r0 + 8) * 512 + c0 * 4) = make_float2(acc[mt][nt][2], acc[mt][nt][3]);
        }
    __syncthreads();

    // att1 sums: warp w handles rows w*8..w*8+7
    float aS0 = attS[lane], aS1 = attS[32 + lane], aS2 = attS[64 + lane], aS3 = attS[96 + lane];
    float aD0 = attD[lane], aD1 = attD[32 + lane], aD2 = attD[64 + lane], aD3 = attD[96 + lane];
    for (int rr = 0; rr < 8; rr++) {
        int r = wid * 8 + rr;
        int gr = rowBase + r;
        const float* hp = (const float*)(smem + r * 512);
        float h0 = hp[lane], h1 = hp[32 + lane], h2 = hp[64 + lane], h3 = hp[96 + lane];
        float s0 = h0 * aS0, s1 = h1 * aS1, s2 = h2 * aS2, s3 = h3 * aS3;
        float d0 = h0 * aD0, d1 = h1 * aD1, d2 = h2 * aD2, d3 = h3 * aD3;
        #pragma unroll
        for (int o = 16; o; o >>= 1) {
            s0 += __shfl_xor_sync(0xffffffffu, s0, o);
            s1 += __shfl_xor_sync(0xffffffffu, s1, o);
            s2 += __shfl_xor_sync(0xffffffffu, s2, o);
            s3 += __shfl_xor_sync(0xffffffffu, s3, o);
            d0 += __shfl_xor_sync(0xffffffffu, d0, o);
            d1 += __shfl_xor_sync(0xffffffffu, d1, o);
            d2 += __shfl_xor_sync(0xffffffffu, d2, o);
            d3 += __shfl_xor_sync(0xffffffffu, d3, o);
        }
        if (lane == 0 && gr < M) {
            *(float4*)(g_as1 + gr * 4) = make_float4(s0, s1, s2, s3);
            *(float4*)(g_ad1 + gr * 4) = make_float4(d0, d1, d2, d3);
        }
    }

    // h1th store: 2048 = 64 rows x 32 ch
    #pragma unroll
    for (int i = 0; i < 8; i++) {
        int idx = i * 256 + tid;
        int r = idx >> 5, ch = idx & 31;
        int gr = rowBase + r;
        if (gr < M) {
            const float* hp = (const float*)(smem + r * 512);
            u64 pk = (u64)__half_as_ushort(__float2half_rn(hp[ch]))
                   | ((u64)__half_as_ushort(__float2half_rn(hp[32 + ch])) << 16)
                   | ((u64)__half_as_ushort(__float2half_rn(hp[64 + ch])) << 32)
                   | ((u64)__half_as_ushort(__float2half_rn(hp[96 + ch])) << 48);
            *(u64*)(g_h1th + gr * 128 + ch * 4) = pk;
        }
    }
}

// ---------------- fused agg1 + GEMM2 (+att2 epi) — R15 proven form -----------
__global__ __launch_bounds__(256) void agg1_gemm2_kernel(
    const float* __restrict__ b1,
    const float* __restrict__ attS, const float* __restrict__ attD, int M)
{
    extern __shared__ char smem[];
    __shared__ float4 wbuf[8][32];
    __shared__ int    sbuf[8][32];
    u32 sb = smem_u32(smem);
    int tid = threadIdx.x, lane = tid & 31, wid = tid >> 5;
    int wm = wid >> 2, wn = wid & 3;          // 2x4 warp grid, warp tile 32x16
    int rowBase = blockIdx.x * 64;

    // B (W2 hi/lo, 64x128) via cp.async — overlaps the whole aggregation phase
    #pragma unroll
    for (int i = 0; i < 4; i++) {
        int idx = i * 256 + tid;              // 1024 = 64 rows x 16 c
        int row = idx >> 4, c = idx & 15;
        u32 dst = row * 256 + ((u32)(c ^ (row & 7)) << 4);
        cpasync16(smem + SM2_BH + dst, g_w2h + row * 128 + c * 8);
        cpasync16(smem + SM2_BL + dst, g_w2l + row * 128 + c * 8);
    }
    CP_COMMIT();

    // ---- aggregation: warp wid handles nodes rowBase + wid*8 .. +7 ----
    const char* h1b = (const char*)g_h1th;
    float b1v0 = b1[lane], b1v1 = b1[32 + lane], b1v2 = b1[64 + lane], b1v3 = b1[96 + lane];
    for (int t = 0; t < 8; t++) {
        int r = wid * 8 + t;
        int node = rowBase + r;
        if (node >= M) break;
        float4 ad = *(const float4*)(g_ad1 + node * 4);
        int deg = g_cur[node]; if (deg > SLOTS) deg = SLOTS;
        const int* ep = g_ell + node * SLOTS;
        float s0 = 0.f, s1 = 0.f, s2 = 0.f, s3 = 0.f;
        float a0 = 0.f, a1 = 0.f, a2 = 0.f, a3 = 0.f;

        for (int base = 0; base < deg; base += 32) {
            int i = base + lane;
            float4 wv = make_float4(0.f, 0.f, 0.f, 0.f);
            int off = 0;
            if (i < deg) {
                int src = ep[i];
                float4 asv = *(const float4*)(g_as1 + src * 4);
                float e;
                e = asv.x + ad.x; e = e > 0.f ? e : 0.2f * e; wv.x = __expf(fminf(e, 80.f));
                e = asv.y + ad.y; e = e > 0.f ? e : 0.2f * e; wv.y = __expf(fminf(e, 80.f));
                e = asv.z + ad.z; e = e > 0.f ? e : 0.2f * e; wv.z = __expf(fminf(e, 80.f));
                e = asv.w + ad.w; e = e > 0.f ? e : 0.2f * e; wv.w = __expf(fminf(e, 80.f));
                off = src * 256;              // byte offset of h1th row
            }
            wbuf[wid][lane] = wv;
            sbuf[wid][lane] = off;
            __syncwarp();
            int cnt = deg - base; if (cnt > 32) cnt = 32;
            int cnt4 = (cnt + 3) & ~3;        // pad: extra lanes staged w=0,off=0
            for (int j = 0; j < cnt4; j += 4) {
                #pragma unroll
                for (int u = 0; u < 4; u++) {
                    float4 q = wbuf[wid][j + u];
                    const __half2* hp = (const __half2*)(h1b + sbuf[wid][j + u] + lane * 8);
                    float2 f01 = __half22float2(hp[0]);
                    float2 f23 = __half22float2(hp[1]);
                    s0 += q.x; a0 = fmaf(q.x, f01.x, a0);
                    s1 += q.y; a1 = fmaf(q.y, f01.y, a1);
                    s2 += q.z; a2 = fmaf(q.z, f23.x, a2);
                    s3 += q.w; a3 = fmaf(q.w, f23.y, a3);
                }
            }
            __syncwarp();
        }
        // hmid -> smem A tile (bf16 hi/lo, swizzled); channel c = head*32+lane
        float o; u16 h, l; u32 off;
        #define STAGE(oexpr, c) \
            o = (oexpr); o = fmaxf(o, 0.f); bfsplit(o, h, l); \
            off = r * 256 + ((u32)((((c) >> 3) ^ (r & 7))) << 4) + ((c) & 7) * 2; \
            *(u16*)(smem + SM2_AH + off) = h; *(u16*)(smem + SM2_AL + off) = l;
        STAGE(a0 / s0 + b1v0, lane)
        STAGE(a1 / s1 + b1v1, 32 + lane)
        STAGE(a2 / s2 + b1v2, 64 + lane)
        STAGE(a3 / s3 + b1v3, 96 + lane)
        #undef STAGE
    }
    CP_WAIT0();
    __syncthreads();

    // ---- GEMM: hmid(smem) @ W2 ----
    float acc[2][2][4];
    #pragma unroll
    for (int mt = 0; mt < 2; mt++)
        #pragma unroll
        for (int nt = 0; nt < 2; nt++)
            #pragma unroll
            for (int q = 0; q < 4; q++) acc[mt][nt][q] = 0.f;

    #pragma unroll
    for (int kt = 0; kt < 8; kt++) {
        u32 ahi[2][4], alo[2][4], bhi[4], blo[4];
        #pragma unroll
        for (int mt = 0; mt < 2; mt++) {
            int row = wm * 32 + mt * 16 + (lane & 15);
            int c = kt * 2 + (lane >> 4);
            u32 off = row * 256 + ((c ^ (row & 7)) << 4);
            ldm4(sb + SM2_AH + off, ahi[mt][0], ahi[mt][1], ahi[mt][2], ahi[mt][3]);
            ldm4(sb + SM2_AL + off, alo[mt][0], alo[mt][1], alo[mt][2], alo[mt][3]);
        }
        {
            int nn = wn * 16 + ((lane >> 4) << 3) + (lane & 7);
            int c = kt * 2 + ((lane >> 3) & 1);
            u32 off = nn * 256 + ((c ^ (nn & 7)) << 4);
            ldm4(sb + SM2_BH + off, bhi[0], bhi[1], bhi[2], bhi[3]);
            ldm4(sb + SM2_BL + off, blo[0], blo[1], blo[2], blo[3]);
        }
        #pragma unroll
        for (int mt = 0; mt < 2; mt++)
            #pragma unroll
            for (int nt = 0; nt < 2; nt++) {
                int sel = nt * 2;
                mma_bf16(acc[mt][nt], ahi[mt], bhi[sel], bhi[sel + 1]);
                mma_bf16(acc[mt][nt], ahi[mt], blo[sel], blo[sel + 1]);
                mma_bf16(acc[mt][nt], alo[mt], bhi[sel], bhi[sel + 1]);
            }
    }
    __syncthreads();

    // stage H fp32 [64][64] stride 256B (reuses A region)
    #pragma unroll
    for (int mt = 0; mt < 2; mt++)
        #pragma unroll
        for (int nt = 0; nt < 2; nt++) {
            int r0 = wm * 32 + mt * 16 + (lane >> 2);
            int c0 = wn * 16 + nt * 8 + (lane & 3) * 2;
            *(float2*)(smem + r0 * 256 + c0 * 4) = make_float2(acc[mt][nt][0], acc[mt][nt][1]);
            *(float2*)(smem + (r0 + 8) * 256 + c0 * 4) = make_float2(acc[mt][nt][2], acc[mt][nt][3]);
        }
    __syncthreads();

    float aS0 = attS[lane], aS1 = attS[32 + lane];
    float aD0 = attD[lane], aD1 = attD[32 + lane];
    for (int rr = 0; rr < 8; rr++) {
        int r = wid * 8 + rr;
        int gr = rowBase + r;
        const float* hp = (const float*)(smem + r * 256);
        float h0 = hp[lane], h1 = hp[32 + lane];
        float sp = h0 * aS0 + h1 * aS1;
        float dp = h0 * aD0 + h1 * aD1;
        #pragma unroll
        for (int o = 16; o; o >>= 1) {
            sp += __shfl_xor_sync(0xffffffffu, sp, o);
            dp += __shfl_xor_sync(0xffffffffu, dp, o);
        }
        if (gr < M) {
            *(__half2*)(g_h2th + gr * 64 + lane * 2) = __floats2half2_rn(h0, h1);
            if (lane == 0) { g_as2[gr] = sp; g_ad2[gr] = dp; }
        }
    }
}

// ---------------- agg2: 2 nodes per warp (16-lane groups, no combines) -------
__global__ __launch_bounds__(256) void agg2_kernel(const float* __restrict__ b2,
                                                   float* __restrict__ out, int n) {
    __shared__ float2 wbuf[8][32];
    int w = threadIdx.x >> 5, lane = threadIdx.x & 31;
    int eh = lane >> 4, lc = lane & 15;
    int node = blockIdx.x * 16 + w * 2 + eh;
    bool active = node < n;
    float ad = 0.f;
    int deg = 0;
    const int* ep = g_ell;
    if (active) {
        ad = g_ad2[node];
        deg = g_cur[node]; if (deg > SLOTS) deg = SLOTS;
        ep = g_ell + node * SLOTS;
    }
    // warp-uniform outer bound
    int degw = deg;
    degw = max(degw, __shfl_xor_sync(0xffffffffu, degw, 16));
    degw = max(degw, __shfl_xor_sync(0xffffffffu, degw, 8));
    degw = max(degw, __shfl_xor_sync(0xffffffffu, degw, 4));
    degw = max(degw, __shfl_xor_sync(0xffffffffu, degw, 2));
    degw = max(degw, __shfl_xor_sync(0xffffffffu, degw, 1));

    const char* h2b = (const char*)g_h2th;
    float b2a = b2[lc * 2], b2b = b2[lc * 2 + 1];
    float b2c = b2[32 + lc * 2], b2d = b2[32 + lc * 2 + 1];
    float s = 0.f, a0 = 0.f, a1 = 0.f, a2 = 0.f, a3 = 0.f;

    for (int base = 0; base < degw; base += 16) {
        int i = base + lc;
        float wv = 0.f; int off = 0;
        if (i < deg) {
            int src = ep[i];
            float e = g_as2[src] + ad;
            e = e > 0.f ? e : 0.2f * e;
            wv = __expf(fminf(e, 80.f));
            off = src * 128;                  // byte offset of h2th row
        }
        wbuf[w][lane] = make_float2(wv, __int_as_float(off));
        __syncwarp();
        int cnt = deg - base;
        if (cnt > 16) cnt = 16;
        if (cnt < 0) cnt = 0;
        int cnt2 = (cnt + 1) & ~1;            // pad: staged w=0,off=0
        const float2* myq = &wbuf[w][eh * 16];
        for (int j = 0; j < cnt2; j += 2) {
            #pragma unroll
            for (int u = 0; u < 2; u++) {
                float2 qo = myq[j + u];
                float q = qo.x;
                const __half2* hp = (const __half2*)(h2b + __float_as_int(qo.y) + lc * 8);
                float2 v01 = __half22float2(hp[0]);  // ch lc*2, lc*2+32
                float2 v23 = __half22float2(hp[1]);  // ch lc*2+1, lc*2+33
                s += q;
                a0 = fmaf(q, v01.x, a0); a1 = fmaf(q, v01.y, a1);
                a2 = fmaf(q, v23.x, a2); a3 = fmaf(q, v23.y, a3);
            }
        }
        __syncwarp();
    }
    if (active) {
        float r = 1.f / s;
        *(float2*)(out + node * 64 + lc * 2) =
            make_float2(a0 * r + b2a, a2 * r + b2b);
        *(float2*)(out + node * 64 + 32 + lc * 2) =
            make_float2(a1 * r + b2c, a3 * r + b2d);
    }
}

// ---------------- launch -----------------------------------------------------
extern "C" void kernel_launch(void* const* d_in, const int* in_sizes, int n_in,
                              void* d_out, int out_size) {
    const float* x    = (const float*)d_in[0];
    const int*   esrc = (const int*)d_in[1];
    const int*   edst = (const int*)d_in[2];
    const float* W1   = (const float*)d_in[3];
    const float* as1w = (const float*)d_in[4];
    const float* ad1w = (const float*)d_in[5];
    const float* b1   = (const float*)d_in[6];
    const float* W2   = (const float*)d_in[7];
    const float* as2w = (const float*)d_in[8];
    const float* ad2w = (const float*)d_in[9];
    const float* b2   = (const float*)d_in[10];
    float* out = (float*)d_out;

    int n = in_sizes[0] / 128;
    int E = in_sizes[1];

    cudaFuncSetAttribute(gemm1_fill_kernel,
                         cudaFuncAttributeMaxDynamicSharedMemorySize, SM_TOTAL);
    cudaFuncSetAttribute(agg1_gemm2_kernel,
                         cudaFuncAttributeMaxDynamicSharedMemorySize, SM2_TOTAL);

    int zb = (n + 255) / 256;
    prep_kernel<<<zb + 12, 256>>>(W1, W2, n, zb);

    int gemmBlocks = (n + 63) / 64;
    int fillBlocks = (E + 4095) / 4096;
    gemm1_fill_kernel<<<gemmBlocks + fillBlocks, 256, SM_TOTAL>>>(
        x, as1w, ad1w, esrc, edst, n, E, gemmBlocks);
    agg1_gemm2_kernel<<<gemmBlocks, 256, SM2_TOTAL>>>(b1, as2w, ad2w, n);
    int aggBlocks = (n + 15) / 16;
    agg2_kernel<<<aggBlocks, 256>>>(b2, out, n);
}